// round 6
// baseline (speedup 1.0000x reference)
#include <cuda_runtime.h>
#include <cuda_bf16.h>
#include <cstdint>

#define IN_F   4096
#define OUT_F  4096
#define BATCH  8192
#define DF     64
#define NT     32      // number of 128-wide output tiles
#define KW     256     // K window per tile
#define TM     128     // rows per block
#define TN     128     // output cols per block
#define KC     32      // K chunk
#define PAD    40      // padded smem row (bf16 elems)

// Packed banded weights, split into hi/lo bf16. Layout: [tile][n][k] (k contiguous,
// i.e. "col-major B" for mma.row.col).
__device__ __align__(16) __nv_bfloat16 g_whi[NT][TN][KW];
__device__ __align__(16) __nv_bfloat16 g_wlo[NT][TN][KW];

__device__ __forceinline__ int tile_start(int t) {
    int s = t * TN - DF;
    if (s < 0) s = 0;
    if (s > IN_F - KW) s = IN_F - KW;
    return s;
}

__global__ void prep_kernel(const float* __restrict__ w,
                            const float* __restrict__ mask) {
    int idx = blockIdx.x * blockDim.x + threadIdx.x;
    if (idx >= NT * TN * KW) return;
    int t = idx / (TN * KW);
    int n = (idx / KW) % TN;
    int k = idx % KW;
    int s = tile_start(t);
    int o = t * TN + n;
    int i = s + k;
    size_t off = (size_t)o * IN_F + i;
    float v = w[off] * mask[off];
    __nv_bfloat16 hi = __float2bfloat16(v);
    __nv_bfloat16 lo = __float2bfloat16(v - __bfloat162float(hi));
    g_whi[t][n][k] = hi;
    g_wlo[t][n][k] = lo;
}

#define MMA_BF16(c, a, b)                                                     \
    asm volatile(                                                             \
        "mma.sync.aligned.m16n8k16.row.col.f32.bf16.bf16.f32 "                \
        "{%0,%1,%2,%3}, {%4,%5,%6,%7}, {%8,%9}, {%0,%1,%2,%3};\n"             \
        : "+f"((c)[0]), "+f"((c)[1]), "+f"((c)[2]), "+f"((c)[3])              \
        : "r"((a)[0]), "r"((a)[1]), "r"((a)[2]), "r"((a)[3]),                 \
          "r"((b)[0]), "r"((b)[1]))

__global__ __launch_bounds__(256, 1)
void band_gemm_kernel(const float* __restrict__ x,
                      const float* __restrict__ bias,
                      float* __restrict__ out) {
    __shared__ __align__(16) __nv_bfloat16 sXhi[TM][PAD];
    __shared__ __align__(16) __nv_bfloat16 sXlo[TM][PAD];
    __shared__ __align__(16) __nv_bfloat16 sWhi[TN][PAD];
    __shared__ __align__(16) __nv_bfloat16 sWlo[TN][PAD];

    const int t  = blockIdx.y;          // output tile
    const int rt = blockIdx.x;          // row tile
    const int s  = tile_start(t);

    const int tid  = threadIdx.x;
    const int lane = tid & 31;
    const int warp = tid >> 5;
    const int wm = warp >> 2;           // 0..1 : 64-row slab
    const int wn = warp & 3;            // 0..3 : 32-col slab
    const int g  = lane >> 2;           // group id 0..7
    const int t4 = lane & 3;            // 0..3

    float acc[4][4][4];
    #pragma unroll
    for (int mf = 0; mf < 4; mf++)
        #pragma unroll
        for (int nf = 0; nf < 4; nf++)
            #pragma unroll
            for (int e = 0; e < 4; e++) acc[mf][nf][e] = 0.0f;

    for (int kc = 0; kc < KW; kc += KC) {
        // ---- load X chunk [128 x 32] fp32, split to bf16 hi/lo in smem ----
        {
            int row = tid >> 1;               // 0..127
            int qb  = (tid & 1) * 16;         // starting k within chunk
            const float4* src = (const float4*)(x + (size_t)(rt * TM + row) * IN_F
                                                + s + kc + qb);
            #pragma unroll
            for (int j = 0; j < 4; j++) {
                float4 v = src[j];
                int kk = qb + j * 4;
                __nv_bfloat16 hx = __float2bfloat16(v.x);
                __nv_bfloat16 hy = __float2bfloat16(v.y);
                __nv_bfloat16 hz = __float2bfloat16(v.z);
                __nv_bfloat16 hw = __float2bfloat16(v.w);
                __nv_bfloat162 h01, h23, l01, l23;
                h01.x = hx; h01.y = hy; h23.x = hz; h23.y = hw;
                l01.x = __float2bfloat16(v.x - __bfloat162float(hx));
                l01.y = __float2bfloat16(v.y - __bfloat162float(hy));
                l23.x = __float2bfloat16(v.z - __bfloat162float(hz));
                l23.y = __float2bfloat16(v.w - __bfloat162float(hw));
                *(__nv_bfloat162*)&sXhi[row][kk]     = h01;
                *(__nv_bfloat162*)&sXhi[row][kk + 2] = h23;
                *(__nv_bfloat162*)&sXlo[row][kk]     = l01;
                *(__nv_bfloat162*)&sXlo[row][kk + 2] = l23;
            }
        }
        // ---- load W chunk [128 n x 32 k] bf16 hi/lo ----
        {
            #pragma unroll
            for (int rep = 0; rep < 2; rep++) {
                int u  = tid + rep * 256;     // 0..511
                int n  = u >> 2;
                int kq = u & 3;
                *(uint4*)&sWhi[n][kq * 8] = *(const uint4*)&g_whi[t][n][kc + kq * 8];
                *(uint4*)&sWlo[n][kq * 8] = *(const uint4*)&g_wlo[t][n][kc + kq * 8];
            }
        }
        __syncthreads();

        // ---- compute: 2 k-steps of 16 ----
        #pragma unroll
        for (int ks = 0; ks < 2; ks++) {
            const int kb = ks * 16;
            uint32_t bh[4][2], bl[4][2];
            #pragma unroll
            for (int nf = 0; nf < 4; nf++) {
                int n = wn * 32 + nf * 8 + g;
                bh[nf][0] = *(const uint32_t*)&sWhi[n][kb + 2 * t4];
                bh[nf][1] = *(const uint32_t*)&sWhi[n][kb + 8 + 2 * t4];
                bl[nf][0] = *(const uint32_t*)&sWlo[n][kb + 2 * t4];
                bl[nf][1] = *(const uint32_t*)&sWlo[n][kb + 8 + 2 * t4];
            }
            #pragma unroll
            for (int mf = 0; mf < 4; mf++) {
                int r0 = wm * 64 + mf * 16 + g;
                uint32_t ah[4], al[4];
                ah[0] = *(const uint32_t*)&sXhi[r0][kb + 2 * t4];
                ah[1] = *(const uint32_t*)&sXhi[r0 + 8][kb + 2 * t4];
                ah[2] = *(const uint32_t*)&sXhi[r0][kb + 8 + 2 * t4];
                ah[3] = *(const uint32_t*)&sXhi[r0 + 8][kb + 8 + 2 * t4];
                al[0] = *(const uint32_t*)&sXlo[r0][kb + 2 * t4];
                al[1] = *(const uint32_t*)&sXlo[r0 + 8][kb + 2 * t4];
                al[2] = *(const uint32_t*)&sXlo[r0][kb + 8 + 2 * t4];
                al[3] = *(const uint32_t*)&sXlo[r0 + 8][kb + 8 + 2 * t4];
                #pragma unroll
                for (int nf = 0; nf < 4; nf++) {
                    MMA_BF16(acc[mf][nf], ah, bh[nf]);   // xhi * whi
                    MMA_BF16(acc[mf][nf], ah, bl[nf]);   // xhi * wlo
                    MMA_BF16(acc[mf][nf], al, bh[nf]);   // xlo * whi
                }
            }
        }
        __syncthreads();
    }

    // ---- epilogue: add bias, store fp32 ----
    #pragma unroll
    for (int mf = 0; mf < 4; mf++) {
        int r = rt * TM + wm * 64 + mf * 16 + g;
        #pragma unroll
        for (int nf = 0; nf < 4; nf++) {
            int c = t * TN + wn * 32 + nf * 8 + 2 * t4;
            float2 bb = *(const float2*)&bias[c];
            float2 v0, v1;
            v0.x = acc[mf][nf][0] + bb.x;
            v0.y = acc[mf][nf][1] + bb.y;
            v1.x = acc[mf][nf][2] + bb.x;
            v1.y = acc[mf][nf][3] + bb.y;
            *(float2*)&out[(size_t)r * OUT_F + c]       = v0;
            *(float2*)&out[(size_t)(r + 8) * OUT_F + c] = v1;
        }
    }
}

extern "C" void kernel_launch(void* const* d_in, const int* in_sizes, int n_in,
                              void* d_out, int out_size) {
    const float* x    = (const float*)d_in[0];
    const float* w    = (const float*)d_in[1];
    const float* bias = (const float*)d_in[2];
    const float* mask = (const float*)d_in[3];
    float* out = (float*)d_out;

    prep_kernel<<<(NT * TN * KW + 255) / 256, 256>>>(w, mask);
    band_gemm_kernel<<<dim3(BATCH / TM, NT), 256>>>(x, bias, out);
}

// round 7
// speedup vs baseline: 1.2238x; 1.2238x over previous
#include <cuda_runtime.h>
#include <cuda_bf16.h>
#include <cstdint>

#define IN_F   4096
#define OUT_F  4096
#define BATCH  8192
#define DF     64
#define NT     32      // number of 128-wide output tiles
#define KW     256     // K window per tile
#define TM     128     // rows per block
#define TN     128     // output cols per block
#define KC     32      // K chunk
#define NCH    (KW/KC) // 8 chunks
#define PAD    40      // padded smem row (bf16 elems)

// Packed banded weights, split into hi/lo bf16. Layout: [tile][n][k].
__device__ __align__(16) __nv_bfloat16 g_whi[NT][TN][KW];
__device__ __align__(16) __nv_bfloat16 g_wlo[NT][TN][KW];

__device__ __forceinline__ int tile_start(int t) {
    int s = t * TN - DF;
    if (s < 0) s = 0;
    if (s > IN_F - KW) s = IN_F - KW;
    return s;
}

__global__ void prep_kernel(const float* __restrict__ w,
                            const float* __restrict__ mask) {
    int idx = blockIdx.x * blockDim.x + threadIdx.x;
    if (idx >= NT * TN * KW) return;
    int t = idx / (TN * KW);
    int n = (idx / KW) % TN;
    int k = idx % KW;
    int s = tile_start(t);
    int o = t * TN + n;
    int i = s + k;
    size_t off = (size_t)o * IN_F + i;
    float v = w[off] * mask[off];
    __nv_bfloat16 hi = __float2bfloat16(v);
    __nv_bfloat16 lo = __float2bfloat16(v - __bfloat162float(hi));
    g_whi[t][n][k] = hi;
    g_wlo[t][n][k] = lo;
}

struct __align__(16) Smem {
    __nv_bfloat16 xhi[2][TM][PAD];   // byte offset 0,     buf stride 10240
    __nv_bfloat16 xlo[2][TM][PAD];   // byte offset 20480
    __nv_bfloat16 whi[2][TN][PAD];   // byte offset 40960
    __nv_bfloat16 wlo[2][TN][PAD];   // byte offset 61440
};
#define SMEM_BYTES (sizeof(Smem))    // 81920

__device__ __forceinline__ void cp16(void* dst, const void* src) {
    uint32_t d = (uint32_t)__cvta_generic_to_shared(dst);
    asm volatile("cp.async.cg.shared.global [%0], [%1], 16;\n" :: "r"(d), "l"(src));
}

__device__ __forceinline__ void ldmx4(uint32_t* r, uint32_t addr) {
    asm volatile("ldmatrix.sync.aligned.m8n8.x4.shared.b16 {%0,%1,%2,%3}, [%4];\n"
                 : "=r"(r[0]), "=r"(r[1]), "=r"(r[2]), "=r"(r[3]) : "r"(addr));
}

#define MMA_BF16(c, a, b)                                                     \
    asm volatile(                                                             \
        "mma.sync.aligned.m16n8k16.row.col.f32.bf16.bf16.f32 "                \
        "{%0,%1,%2,%3}, {%4,%5,%6,%7}, {%8,%9}, {%0,%1,%2,%3};\n"             \
        : "+f"((c)[0]), "+f"((c)[1]), "+f"((c)[2]), "+f"((c)[3])              \
        : "r"((a)[0]), "r"((a)[1]), "r"((a)[2]), "r"((a)[3]),                 \
          "r"((b)[0]), "r"((b)[1]))

__global__ __launch_bounds__(256, 1)
void band_gemm_kernel(const float* __restrict__ x,
                      const float* __restrict__ bias,
                      float* __restrict__ out) {
    extern __shared__ char smem_raw[];
    Smem* sm = (Smem*)smem_raw;

    const int t  = blockIdx.y;          // output tile
    const int rt = blockIdx.x;          // row tile
    const int s  = tile_start(t);

    const int tid  = threadIdx.x;
    const int lane = tid & 31;
    const int warp = tid >> 5;
    const int wm = warp >> 2;           // 0..1 : 64-row slab
    const int wn = warp & 3;            // 0..3 : 32-col slab
    const int g  = lane >> 2;           // group id 0..7
    const int t4 = lane & 3;            // 0..3

    // ldmatrix per-lane base byte offsets (within one buffer)
    // A x4: lanes 0-7 rows r..r+7 @k-lo | 8-15 rows+8 @k-lo | 16-23 rows @k-hi | 24-31 rows+8 @k-hi
    const int aoff = ((wm * 64 + (lane & 7) + ((lane >> 3) & 1) * 8) * PAD
                      + ((lane >> 4) & 1) * 8) * 2;
    // B x4: lanes 0-7 rows n..n+7 @k-lo | 8-15 same rows @k-hi | 16-23 rows+8 @k-lo | 24-31 rows+8 @k-hi
    const int boff = ((wn * 32 + (lane & 7) + ((lane >> 4) & 1) * 8) * PAD
                      + ((lane >> 3) & 1) * 8) * 2;

    const uint32_t sb  = (uint32_t)__cvta_generic_to_shared(smem_raw);
    const uint32_t XHI = sb;
    const uint32_t XLO = sb + 20480u;
    const uint32_t WHI = sb + 40960u;
    const uint32_t WLO = sb + 61440u;

    float acc[4][4][4];
    #pragma unroll
    for (int mf = 0; mf < 4; mf++)
        #pragma unroll
        for (int nf = 0; nf < 4; nf++)
            #pragma unroll
            for (int e = 0; e < 4; e++) acc[mf][nf][e] = 0.0f;

    const int xrw = tid >> 1;               // 0..127
    const int qb  = (tid & 1) * 16;
    const float* xrow = x + (size_t)(rt * TM + xrw) * IN_F + s + qb;

    const int wi = tid * 2;                 // cp.async work: 2 units/thread/array
    const int wn0 = wi >> 2,      wk0 = (wi & 3) * 8;
    const int wn1 = (wi + 1) >> 2, wk1 = ((wi + 1) & 3) * 8;

    // ---- prologue: prefetch chunk 0 ----
    float4 xr[4];
    #pragma unroll
    for (int j = 0; j < 4; j++) xr[j] = *(const float4*)(xrow + j * 4);
    cp16(&sm->whi[0][wn0][wk0], &g_whi[t][wn0][wk0]);
    cp16(&sm->wlo[0][wn0][wk0], &g_wlo[t][wn0][wk0]);
    cp16(&sm->whi[0][wn1][wk1], &g_whi[t][wn1][wk1]);
    cp16(&sm->wlo[0][wn1][wk1], &g_wlo[t][wn1][wk1]);
    asm volatile("cp.async.commit_group;\n" ::: "memory");

    for (int ci = 0; ci < NCH; ci++) {
        const int b = ci & 1;

        // ---- convert prefetched X regs -> smem buf b ----
        #pragma unroll
        for (int j = 0; j < 4; j++) {
            float4 v = xr[j];
            int kk = qb + j * 4;
            __nv_bfloat16 hx = __float2bfloat16(v.x);
            __nv_bfloat16 hy = __float2bfloat16(v.y);
            __nv_bfloat16 hz = __float2bfloat16(v.z);
            __nv_bfloat16 hw = __float2bfloat16(v.w);
            __nv_bfloat162 h01, h23, l01, l23;
            h01.x = hx; h01.y = hy; h23.x = hz; h23.y = hw;
            l01.x = __float2bfloat16(v.x - __bfloat162float(hx));
            l01.y = __float2bfloat16(v.y - __bfloat162float(hy));
            l23.x = __float2bfloat16(v.z - __bfloat162float(hz));
            l23.y = __float2bfloat16(v.w - __bfloat162float(hw));
            *(__nv_bfloat162*)&sm->xhi[b][xrw][kk]     = h01;
            *(__nv_bfloat162*)&sm->xhi[b][xrw][kk + 2] = h23;
            *(__nv_bfloat162*)&sm->xlo[b][xrw][kk]     = l01;
            *(__nv_bfloat162*)&sm->xlo[b][xrw][kk + 2] = l23;
        }

        asm volatile("cp.async.wait_group 0;\n" ::: "memory");
        __syncthreads();

        // ---- prefetch chunk ci+1 (X -> regs, W -> smem buf b^1) ----
        if (ci + 1 < NCH) {
            const int kn = (ci + 1) * KC;
            #pragma unroll
            for (int j = 0; j < 4; j++) xr[j] = *(const float4*)(xrow + kn + j * 4);
            const int nb = b ^ 1;
            cp16(&sm->whi[nb][wn0][wk0], &g_whi[t][wn0][kn + wk0]);
            cp16(&sm->wlo[nb][wn0][wk0], &g_wlo[t][wn0][kn + wk0]);
            cp16(&sm->whi[nb][wn1][wk1], &g_whi[t][wn1][kn + wk1]);
            cp16(&sm->wlo[nb][wn1][wk1], &g_wlo[t][wn1][kn + wk1]);
            asm volatile("cp.async.commit_group;\n" ::: "memory");
        }

        // ---- compute chunk ci on buf b ----
        const uint32_t bufo = (uint32_t)b * 10240u;
        #pragma unroll
        for (int ks = 0; ks < 2; ks++) {
            uint32_t bh[8], bl[8];
            #pragma unroll
            for (int np = 0; np < 2; np++) {
                uint32_t tmp[4];
                ldmx4(tmp, WHI + bufo + boff + np * 1280 + ks * 32);
                bh[np * 4 + 0] = tmp[0]; bh[np * 4 + 1] = tmp[1];
                bh[np * 4 + 2] = tmp[2]; bh[np * 4 + 3] = tmp[3];
                ldmx4(tmp, WLO + bufo + boff + np * 1280 + ks * 32);
                bl[np * 4 + 0] = tmp[0]; bl[np * 4 + 1] = tmp[1];
                bl[np * 4 + 2] = tmp[2]; bl[np * 4 + 3] = tmp[3];
            }
            #pragma unroll
            for (int mf = 0; mf < 4; mf++) {
                uint32_t ah[4], al[4];
                ldmx4(ah, XHI + bufo + aoff + mf * 1280 + ks * 32);
                ldmx4(al, XLO + bufo + aoff + mf * 1280 + ks * 32);
                #pragma unroll
                for (int nf = 0; nf < 4; nf++) {
                    MMA_BF16(acc[mf][nf], ah, &bh[nf * 2]);   // xhi*whi
                    MMA_BF16(acc[mf][nf], ah, &bl[nf * 2]);   // xhi*wlo
                    MMA_BF16(acc[mf][nf], al, &bh[nf * 2]);   // xlo*whi
                }
            }
        }
        // no trailing barrier needed: next iter writes only the other buffers
        // before its barrier (X-STS -> buf b^1; W cp.async issued post-barrier)
        __syncthreads();
    }

    // ---- epilogue: add bias, store fp32 ----
    #pragma unroll
    for (int mf = 0; mf < 4; mf++) {
        int r = rt * TM + wm * 64 + mf * 16 + g;
        #pragma unroll
        for (int nf = 0; nf < 4; nf++) {
            int c = t * TN + wn * 32 + nf * 8 + 2 * t4;
            float2 bb = *(const float2*)&bias[c];
            float2 v0, v1;
            v0.x = acc[mf][nf][0] + bb.x;
            v0.y = acc[mf][nf][1] + bb.y;
            v1.x = acc[mf][nf][2] + bb.x;
            v1.y = acc[mf][nf][3] + bb.y;
            *(float2*)&out[(size_t)r * OUT_F + c]       = v0;
            *(float2*)&out[(size_t)(r + 8) * OUT_F + c] = v1;
        }
    }
}

extern "C" void kernel_launch(void* const* d_in, const int* in_sizes, int n_in,
                              void* d_out, int out_size) {
    const float* x    = (const float*)d_in[0];
    const float* w    = (const float*)d_in[1];
    const float* bias = (const float*)d_in[2];
    const float* mask = (const float*)d_in[3];
    float* out = (float*)d_out;

    cudaFuncSetAttribute(band_gemm_kernel,
                         cudaFuncAttributeMaxDynamicSharedMemorySize,
                         (int)SMEM_BYTES);

    prep_kernel<<<(NT * TN * KW + 255) / 256, 256>>>(w, mask);
    band_gemm_kernel<<<dim3(BATCH / TM, NT), 256, SMEM_BYTES>>>(x, bias, out);
}

// round 10
// speedup vs baseline: 2.4969x; 2.0403x over previous
#include <cuda_runtime.h>
#include <cuda_fp16.h>
#include <cstdint>

#define IN_F   4096
#define OUT_F  4096
#define BATCH  8192
#define DF     64
#define NT     32      // number of 128-wide output tiles
#define KW     256     // K window per tile
#define TM     128     // rows per block
#define TN     128     // output cols per block
#define KC     32      // K chunk
#define NCH    (KW/KC) // 8 chunks
#define PAD    40      // padded smem row (fp16 elems)
#define NSTG   3       // pipeline stages

// Packed banded weights (mask applied), fp16. Layout: [tile][n][k], K-major.
__device__ __align__(16) __half g_w[NT][TN][KW];

__device__ __forceinline__ int tile_start(int t) {
    int s = t * TN - DF;
    if (s < 0) s = 0;
    if (s > IN_F - KW) s = IN_F - KW;
    return s;
}

__global__ void prep_kernel(const float* __restrict__ w,
                            const float* __restrict__ mask) {
    int idx = blockIdx.x * blockDim.x + threadIdx.x;
    if (idx >= NT * TN * KW) return;
    int t = idx / (TN * KW);
    int n = (idx / KW) % TN;
    int k = idx % KW;
    int s = tile_start(t);
    size_t off = (size_t)(t * TN + n) * IN_F + (s + k);
    g_w[t][n][k] = __float2half(w[off] * mask[off]);
}

struct __align__(16) Smem {
    __half xs[NSTG][TM][PAD];   // A tiles (stage stride 10240 B)
    __half ws[NSTG][TN][PAD];   // B tiles
};
#define SMEM_BYTES (sizeof(Smem))   // 61440

__device__ __forceinline__ void cp16(void* dst, const void* src) {
    uint32_t d = (uint32_t)__cvta_generic_to_shared(dst);
    asm volatile("cp.async.cg.shared.global [%0], [%1], 16;\n" :: "r"(d), "l"(src));
}

__device__ __forceinline__ void ldmx4(uint32_t* r, uint32_t addr) {
    asm volatile("ldmatrix.sync.aligned.m8n8.x4.shared.b16 {%0,%1,%2,%3}, [%4];\n"
                 : "=r"(r[0]), "=r"(r[1]), "=r"(r[2]), "=r"(r[3]) : "r"(addr));
}

#define MMA_F16(c, a, b)                                                      \
    asm volatile(                                                             \
        "mma.sync.aligned.m16n8k16.row.col.f32.f16.f16.f32 "                  \
        "{%0,%1,%2,%3}, {%4,%5,%6,%7}, {%8,%9}, {%0,%1,%2,%3};\n"             \
        : "+f"((c)[0]), "+f"((c)[1]), "+f"((c)[2]), "+f"((c)[3])              \
        : "r"((a)[0]), "r"((a)[1]), "r"((a)[2]), "r"((a)[3]),                 \
          "r"((b)[0]), "r"((b)[1]))

__global__ __launch_bounds__(256, 2)
void band_gemm_kernel(const float* __restrict__ x,
                      const float* __restrict__ bias,
                      float* __restrict__ out) {
    extern __shared__ char smem_raw[];
    Smem* sm = (Smem*)smem_raw;

    const int t  = blockIdx.x;          // output tile (fast dim -> L2-friendly)
    const int rt = blockIdx.y;          // row tile
    const int s  = tile_start(t);

    const int tid  = threadIdx.x;
    const int lane = tid & 31;
    const int warp = tid >> 5;
    const int wm = warp >> 2;           // 0..1 : 64-row slab
    const int wn = warp & 3;            // 0..3 : 32-col slab
    const int g  = lane >> 2;           // 0..7
    const int t4 = lane & 3;            // 0..3

    // ldmatrix per-lane base byte offsets (within one stage)
    const int aoff = ((wm * 64 + (lane & 7) + ((lane >> 3) & 1) * 8) * PAD
                      + ((lane >> 4) & 1) * 8) * 2;
    const int boff = ((wn * 32 + (lane & 7) + ((lane >> 4) & 1) * 8) * PAD
                      + ((lane >> 3) & 1) * 8) * 2;

    const uint32_t sb = (uint32_t)__cvta_generic_to_shared(smem_raw);
    const uint32_t XS = sb;             // xs base
    const uint32_t WS = sb + NSTG * 10240u;

    float acc[4][4][4];
    #pragma unroll
    for (int mf = 0; mf < 4; mf++)
        #pragma unroll
        for (int nf = 0; nf < 4; nf++)
            #pragma unroll
            for (int e = 0; e < 4; e++) acc[mf][nf][e] = 0.0f;

    // X: thread owns (row = tid>>1, 16-wide k-half = (tid&1)*16)
    const int xrw = tid >> 1;
    const int qb  = (tid & 1) * 16;
    const float* xrow = x + (size_t)(rt * TM + xrw) * IN_F + s + qb;

    // W cp.async: 2 x 16B units per thread per chunk
    const int wu  = tid * 2;
    const int wn0 = wu >> 2,       wk0 = (wu & 3) * 8;
    const int wn1 = (wu + 1) >> 2, wk1 = ((wu + 1) & 3) * 8;

    // ---- prologue ----
    float4 xr[4];
    #pragma unroll
    for (int j = 0; j < 4; j++) xr[j] = *(const float4*)(xrow + j * 4);

    cp16(&sm->ws[0][wn0][wk0], &g_w[t][wn0][wk0]);
    cp16(&sm->ws[0][wn1][wk1], &g_w[t][wn1][wk1]);
    asm volatile("cp.async.commit_group;" ::: "memory");
    cp16(&sm->ws[1][wn0][wk0], &g_w[t][wn0][KC + wk0]);
    cp16(&sm->ws[1][wn1][wk1], &g_w[t][wn1][KC + wk1]);
    asm volatile("cp.async.commit_group;" ::: "memory");

    #pragma unroll
    for (int ci = 0; ci < NCH; ci++) {
        const int st = ci % NSTG;

        // convert prefetched X regs -> fp16, STS into stage st
        {
            #pragma unroll
            for (int j = 0; j < 2; j++) {
                float4 v0 = xr[2 * j], v1 = xr[2 * j + 1];
                __half2 p0, p1, p2, p3;
                p0 = __floats2half2_rn(v0.x, v0.y);
                p1 = __floats2half2_rn(v0.z, v0.w);
                p2 = __floats2half2_rn(v1.x, v1.y);
                p3 = __floats2half2_rn(v1.z, v1.w);
                uint4 u;
                u.x = *(uint32_t*)&p0; u.y = *(uint32_t*)&p1;
                u.z = *(uint32_t*)&p2; u.w = *(uint32_t*)&p3;
                *(uint4*)&sm->xs[st][xrw][qb + j * 8] = u;
            }
        }

        // prefetch next X chunk (long-latency, issue early)
        if (ci + 1 < NCH) {
            const int kn = (ci + 1) * KC;
            #pragma unroll
            for (int j = 0; j < 4; j++) xr[j] = *(const float4*)(xrow + kn + j * 4);
        }
        // prefetch W chunk ci+2 into stage (ci+2)%NSTG
        if (ci + 2 < NCH) {
            const int kn = (ci + 2) * KC;
            const int ns = (ci + 2) % NSTG;
            cp16(&sm->ws[ns][wn0][wk0], &g_w[t][wn0][kn + wk0]);
            cp16(&sm->ws[ns][wn1][wk1], &g_w[t][wn1][kn + wk1]);
            asm volatile("cp.async.commit_group;" ::: "memory");
        }

        // wait for W chunk ci (leave later groups in flight)
        if (ci < NCH - 2)
            asm volatile("cp.async.wait_group 2;" ::: "memory");
        else if (ci == NCH - 2)
            asm volatile("cp.async.wait_group 1;" ::: "memory");
        else
            asm volatile("cp.async.wait_group 0;" ::: "memory");
        __syncthreads();

        // ---- compute chunk ci on stage st ----
        const uint32_t so = (uint32_t)st * 10240u;
        uint32_t bh[2][8];
        #pragma unroll
        for (int ks = 0; ks < 2; ks++) {
            #pragma unroll
            for (int np = 0; np < 2; np++)
                ldmx4(&bh[ks][np * 4], WS + so + boff + np * 1280 + ks * 32);
        }
        #pragma unroll
        for (int mf = 0; mf < 4; mf++) {
            uint32_t a0[4], a1[4];
            ldmx4(a0, XS + so + aoff + mf * 1280);
            ldmx4(a1, XS + so + aoff + mf * 1280 + 32);
            #pragma unroll
            for (int nf = 0; nf < 4; nf++) {
                MMA_F16(acc[mf][nf], a0, &bh[0][nf * 2]);
                MMA_F16(acc[mf][nf], a1, &bh[1][nf * 2]);
            }
        }
        __syncthreads();   // all warps done with stage st before it is refilled
    }

    // ---- epilogue: add bias, store fp32 ----
    #pragma unroll
    for (int mf = 0; mf < 4; mf++) {
        int r = rt * TM + wm * 64 + mf * 16 + g;
        #pragma unroll
        for (int nf = 0; nf < 4; nf++) {
            int c = t * TN + wn * 32 + nf * 8 + 2 * t4;
            float2 bb = *(const float2*)&bias[c];
            float2 v0, v1;
            v0.x = acc[mf][nf][0] + bb.x;
            v0.y = acc[mf][nf][1] + bb.y;
            v1.x = acc[mf][nf][2] + bb.x;
            v1.y = acc[mf][nf][3] + bb.y;
            *(float2*)&out[(size_t)r * OUT_F + c]       = v0;
            *(float2*)&out[(size_t)(r + 8) * OUT_F + c] = v1;
        }
    }
}

extern "C" void kernel_launch(void* const* d_in, const int* in_sizes, int n_in,
                              void* d_out, int out_size) {
    const float* x    = (const float*)d_in[0];
    const float* w    = (const float*)d_in[1];
    const float* bias = (const float*)d_in[2];
    const float* mask = (const float*)d_in[3];
    float* out = (float*)d_out;

    cudaFuncSetAttribute(band_gemm_kernel,
                         cudaFuncAttributeMaxDynamicSharedMemorySize,
                         (int)SMEM_BYTES);

    prep_kernel<<<(NT * TN * KW + 255) / 256, 256>>>(w, mask);
    band_gemm_kernel<<<dim3(NT, BATCH / TM), 256, SMEM_BYTES>>>(x, bias, out);
}

// round 14
// speedup vs baseline: 2.8151x; 1.1274x over previous
#include <cuda_runtime.h>
#include <cuda_fp16.h>
#include <cstdint>

#define IN_F   4096
#define OUT_F  4096
#define BATCH  8192
#define DF     64
#define NT     32      // number of 128-wide output tiles
#define KW     256     // K window per tile
#define TM     128     // rows per block
#define TN     128     // output cols per block
#define KC     32      // K chunk
#define NCH    (KW/KC) // 8 chunks
#define PAD    40      // padded smem row (fp16 elems)
#define NSTG   3       // pipeline stages

// Packed banded weights (mask applied), fp16. Layout: [tile][n][k], K-major.
__device__ __align__(16) __half g_w[NT][TN][KW];

__device__ __forceinline__ int tile_start(int t) {
    int s = t * TN - DF;
    if (s < 0) s = 0;
    if (s > IN_F - KW) s = IN_F - KW;
    return s;
}

__global__ void prep_kernel(const float* __restrict__ w,
                            const float* __restrict__ mask) {
    int idx = blockIdx.x * blockDim.x + threadIdx.x;
    if (idx >= NT * TN * KW) return;
    int t = idx / (TN * KW);
    int n = (idx / KW) % TN;
    int k = idx % KW;
    int s = tile_start(t);
    size_t off = (size_t)(t * TN + n) * IN_F + (s + k);
    g_w[t][n][k] = __float2half(w[off] * mask[off]);
}

struct __align__(16) Smem {
    __half xs[NSTG][TM][PAD];   // A tiles (stage stride 10240 B)
    __half ws[NSTG][TN][PAD];   // B tiles
};
#define SMEM_BYTES (sizeof(Smem))   // 61440

__device__ __forceinline__ void cp16(void* dst, const void* src) {
    uint32_t d = (uint32_t)__cvta_generic_to_shared(dst);
    asm volatile("cp.async.cg.shared.global [%0], [%1], 16;\n" :: "r"(d), "l"(src));
}

__device__ __forceinline__ void ldmx4(uint32_t* r, uint32_t addr) {
    asm volatile("ldmatrix.sync.aligned.m8n8.x4.shared.b16 {%0,%1,%2,%3}, [%4];\n"
                 : "=r"(r[0]), "=r"(r[1]), "=r"(r[2]), "=r"(r[3]) : "r"(addr));
}

#define MMA_F16(c, a, b)                                                      \
    asm volatile(                                                             \
        "mma.sync.aligned.m16n8k16.row.col.f32.f16.f16.f32 "                  \
        "{%0,%1,%2,%3}, {%4,%5,%6,%7}, {%8,%9}, {%0,%1,%2,%3};\n"             \
        : "+f"((c)[0]), "+f"((c)[1]), "+f"((c)[2]), "+f"((c)[3])              \
        : "r"((a)[0]), "r"((a)[1]), "r"((a)[2]), "r"((a)[3]),                 \
          "r"((b)[0]), "r"((b)[1]))

__global__ __launch_bounds__(256, 2)
void band_gemm_kernel(const float* __restrict__ x,
                      const float* __restrict__ bias,
                      float* __restrict__ out) {
    extern __shared__ char smem_raw[];
    Smem* sm = (Smem*)smem_raw;

    const int t  = blockIdx.x;          // output tile (fast dim -> L2-friendly)
    const int rt = blockIdx.y;          // row tile
    const int s  = tile_start(t);

    const int tid  = threadIdx.x;
    const int lane = tid & 31;
    const int warp = tid >> 5;
    const int wm = warp >> 2;           // 0..1 : 64-row slab
    const int wn = warp & 3;            // 0..3 : 32-col slab
    const int g  = lane >> 2;           // 0..7
    const int t4 = lane & 3;            // 0..3

    // ldmatrix per-lane base byte offsets (within one stage)
    const int aoff = ((wm * 64 + (lane & 7) + ((lane >> 3) & 1) * 8) * PAD
                      + ((lane >> 4) & 1) * 8) * 2;
    const int boff = ((wn * 32 + (lane & 7) + ((lane >> 4) & 1) * 8) * PAD
                      + ((lane >> 3) & 1) * 8) * 2;

    const uint32_t sb = (uint32_t)__cvta_generic_to_shared(smem_raw);
    const uint32_t XS = sb;             // xs base
    const uint32_t WS = sb + NSTG * 10240u;

    float acc[4][4][4];
    #pragma unroll
    for (int mf = 0; mf < 4; mf++)
        #pragma unroll
        for (int nf = 0; nf < 4; nf++)
            #pragma unroll
            for (int e = 0; e < 4; e++) acc[mf][nf][e] = 0.0f;

    // ---- X: fully coalesced ownership: u = tid + 256j -> row=u>>3, seg=u&7 ----
    // Each warp LDG.128 covers 4 complete rows (4 x 128B lines).
    const int xr0  = tid >> 3;              // base row (advances +32 per j)
    const int xseg = tid & 7;               // 16B segment within 128B row chunk
    const float* xbase = x + (size_t)(rt * TM + xr0) * IN_F + s + xseg * 4;
    // STS.64 target byte offset within stage (advances +32*80 per j)
    const uint32_t xso = (uint32_t)(xr0 * (PAD * 2) + xseg * 8);

    // W cp.async: 2 x 16B units per thread per chunk
    const int wu  = tid * 2;
    const int wn0 = wu >> 2,       wk0 = (wu & 3) * 8;
    const int wn1 = (wu + 1) >> 2, wk1 = ((wu + 1) & 3) * 8;

    // ---- prologue ----
    float4 xr[4];
    #pragma unroll
    for (int j = 0; j < 4; j++)
        xr[j] = *(const float4*)(xbase + (size_t)j * 32 * IN_F);

    cp16(&sm->ws[0][wn0][wk0], &g_w[t][wn0][wk0]);
    cp16(&sm->ws[0][wn1][wk1], &g_w[t][wn1][wk1]);
    asm volatile("cp.async.commit_group;" ::: "memory");
    cp16(&sm->ws[1][wn0][wk0], &g_w[t][wn0][KC + wk0]);
    cp16(&sm->ws[1][wn1][wk1], &g_w[t][wn1][KC + wk1]);
    asm volatile("cp.async.commit_group;" ::: "memory");

    #pragma unroll
    for (int ci = 0; ci < NCH; ci++) {
        const int st = ci % NSTG;

        // convert prefetched X regs -> fp16, STS.64 into stage st
        {
            const uint32_t dst0 = XS + (uint32_t)st * 10240u + xso;
            #pragma unroll
            for (int j = 0; j < 4; j++) {
                float4 v = xr[j];
                __half2 h01 = __floats2half2_rn(v.x, v.y);
                __half2 h23 = __floats2half2_rn(v.z, v.w);
                asm volatile("st.shared.v2.b32 [%0], {%1,%2};"
                    :: "r"(dst0 + (uint32_t)j * 32u * (PAD * 2)),
                       "r"(*(uint32_t*)&h01), "r"(*(uint32_t*)&h23));
            }
        }

        // prefetch next X chunk (long-latency, issue early)
        if (ci + 1 < NCH) {
            const int kn = (ci + 1) * KC;
            #pragma unroll
            for (int j = 0; j < 4; j++)
                xr[j] = *(const float4*)(xbase + kn + (size_t)j * 32 * IN_F);
        }
        // prefetch W chunk ci+2 into stage (ci+2)%NSTG
        if (ci + 2 < NCH) {
            const int kn = (ci + 2) * KC;
            const int ns = (ci + 2) % NSTG;
            cp16(&sm->ws[ns][wn0][wk0], &g_w[t][wn0][kn + wk0]);
            cp16(&sm->ws[ns][wn1][wk1], &g_w[t][wn1][kn + wk1]);
            asm volatile("cp.async.commit_group;" ::: "memory");
        }

        // wait for W chunk ci (leave later groups in flight)
        if (ci < NCH - 2)
            asm volatile("cp.async.wait_group 2;" ::: "memory");
        else if (ci == NCH - 2)
            asm volatile("cp.async.wait_group 1;" ::: "memory");
        else
            asm volatile("cp.async.wait_group 0;" ::: "memory");
        __syncthreads();

        // ---- compute chunk ci on stage st ----
        const uint32_t so = (uint32_t)st * 10240u;
        uint32_t bh[2][8];
        #pragma unroll
        for (int ks = 0; ks < 2; ks++) {
            #pragma unroll
            for (int np = 0; np < 2; np++)
                ldmx4(&bh[ks][np * 4], WS + so + boff + np * 1280 + ks * 32);
        }
        #pragma unroll
        for (int mf = 0; mf < 4; mf++) {
            uint32_t a0[4], a1[4];
            ldmx4(a0, XS + so + aoff + mf * 1280);
            ldmx4(a1, XS + so + aoff + mf * 1280 + 32);
            #pragma unroll
            for (int nf = 0; nf < 4; nf++) {
                MMA_F16(acc[mf][nf], a0, &bh[0][nf * 2]);
                MMA_F16(acc[mf][nf], a1, &bh[1][nf * 2]);
            }
        }
        __syncthreads();   // all warps done with stage st before it is refilled
    }

    // ---- epilogue: add bias, store fp32 ----
    #pragma unroll
    for (int mf = 0; mf < 4; mf++) {
        int r = rt * TM + wm * 64 + mf * 16 + g;
        #pragma unroll
        for (int nf = 0; nf < 4; nf++) {
            int c = t * TN + wn * 32 + nf * 8 + 2 * t4;
            float2 bb = *(const float2*)&bias[c];
            float2 v0, v1;
            v0.x = acc[mf][nf][0] + bb.x;
            v0.y = acc[mf][nf][1] + bb.y;
            v1.x = acc[mf][nf][2] + bb.x;
            v1.y = acc[mf][nf][3] + bb.y;
            *(float2*)&out[(size_t)r * OUT_F + c]       = v0;
            *(float2*)&out[(size_t)(r + 8) * OUT_F + c] = v1;
        }
    }
}

extern "C" void kernel_launch(void* const* d_in, const int* in_sizes, int n_in,
                              void* d_out, int out_size) {
    const float* x    = (const float*)d_in[0];
    const float* w    = (const float*)d_in[1];
    const float* bias = (const float*)d_in[2];
    const float* mask = (const float*)d_in[3];
    float* out = (float*)d_out;

    cudaFuncSetAttribute(band_gemm_kernel,
                         cudaFuncAttributeMaxDynamicSharedMemorySize,
                         (int)SMEM_BYTES);

    prep_kernel<<<(NT * TN * KW + 255) / 256, 256>>>(w, mask);
    band_gemm_kernel<<<dim3(NT, BATCH / TM), 256, SMEM_BYTES>>>(x, bias, out);
}

// round 17
// speedup vs baseline: 2.9020x; 1.0309x over previous
#include <cuda_runtime.h>
#include <cuda_fp16.h>
#include <cstdint>

#define IN_F   4096
#define OUT_F  4096
#define BATCH  8192
#define DF     64
#define NT     32      // number of 128-wide output tiles
#define KW     256     // K window per tile
#define TM     128     // rows per block
#define TN     128     // output cols per block
#define KC     32      // K chunk
#define NCH    (KW/KC) // 8 chunks
#define PAD    40      // padded smem row (fp16 elems)
#define NSTG   4       // pipeline stages (4 -> single barrier per chunk is safe)

// Packed banded weights (mask applied), fp16. Layout: [tile][n][k], K-major.
__device__ __align__(16) __half g_w[NT][TN][KW];

__device__ __forceinline__ int tile_start(int t) {
    int s = t * TN - DF;
    if (s < 0) s = 0;
    if (s > IN_F - KW) s = IN_F - KW;
    return s;
}

__global__ void prep_kernel(const float* __restrict__ w,
                            const float* __restrict__ mask) {
    int idx = blockIdx.x * blockDim.x + threadIdx.x;
    if (idx >= NT * TN * KW) return;
    int t = idx / (TN * KW);
    int n = (idx / KW) % TN;
    int k = idx % KW;
    int s = tile_start(t);
    size_t off = (size_t)(t * TN + n) * IN_F + (s + k);
    g_w[t][n][k] = __float2half(w[off] * mask[off]);
}

struct __align__(16) Smem {
    __half xs[NSTG][TM][PAD];   // A tiles (stage stride 10240 B)
    __half ws[NSTG][TN][PAD];   // B tiles
};
#define SMEM_BYTES (sizeof(Smem))   // 81920

__device__ __forceinline__ void cp16(void* dst, const void* src) {
    uint32_t d = (uint32_t)__cvta_generic_to_shared(dst);
    asm volatile("cp.async.cg.shared.global [%0], [%1], 16;\n" :: "r"(d), "l"(src));
}

__device__ __forceinline__ void ldmx4(uint32_t* r, uint32_t addr) {
    asm volatile("ldmatrix.sync.aligned.m8n8.x4.shared.b16 {%0,%1,%2,%3}, [%4];\n"
                 : "=r"(r[0]), "=r"(r[1]), "=r"(r[2]), "=r"(r[3]) : "r"(addr));
}

#define MMA_F16(c, a, b)                                                      \
    asm volatile(                                                             \
        "mma.sync.aligned.m16n8k16.row.col.f32.f16.f16.f32 "                  \
        "{%0,%1,%2,%3}, {%4,%5,%6,%7}, {%8,%9}, {%0,%1,%2,%3};\n"             \
        : "+f"((c)[0]), "+f"((c)[1]), "+f"((c)[2]), "+f"((c)[3])              \
        : "r"((a)[0]), "r"((a)[1]), "r"((a)[2]), "r"((a)[3]),                 \
          "r"((b)[0]), "r"((b)[1]))

__global__ __launch_bounds__(256, 2)
void band_gemm_kernel(const float* __restrict__ x,
                      const float* __restrict__ bias,
                      float* __restrict__ out) {
    extern __shared__ char smem_raw[];
    Smem* sm = (Smem*)smem_raw;

    const int t  = blockIdx.x;          // output tile (fast dim -> L2-friendly)
    const int rt = blockIdx.y;          // row tile
    const int s  = tile_start(t);

    const int tid  = threadIdx.x;
    const int lane = tid & 31;
    const int warp = tid >> 5;
    const int wm = warp >> 2;           // 0..1 : 64-row slab
    const int wn = warp & 3;            // 0..3 : 32-col slab
    const int g  = lane >> 2;           // 0..7
    const int t4 = lane & 3;            // 0..3

    // ldmatrix per-lane base byte offsets (within one stage)
    const int aoff = ((wm * 64 + (lane & 7) + ((lane >> 3) & 1) * 8) * PAD
                      + ((lane >> 4) & 1) * 8) * 2;
    const int boff = ((wn * 32 + (lane & 7) + ((lane >> 4) & 1) * 8) * PAD
                      + ((lane >> 3) & 1) * 8) * 2;

    const uint32_t sb = (uint32_t)__cvta_generic_to_shared(smem_raw);
    const uint32_t XS = sb;             // xs base
    const uint32_t WS = sb + NSTG * 10240u;

    float acc[4][4][4];
    #pragma unroll
    for (int mf = 0; mf < 4; mf++)
        #pragma unroll
        for (int nf = 0; nf < 4; nf++)
            #pragma unroll
            for (int e = 0; e < 4; e++) acc[mf][nf][e] = 0.0f;

    // ---- X: fully coalesced ownership: u = tid + 256j -> row=u>>3, seg=u&7 ----
    const int xr0  = tid >> 3;              // base row (advances +32 per j)
    const int xseg = tid & 7;               // 16B segment within 128B row chunk
    const float* xbase = x + (size_t)(rt * TM + xr0) * IN_F + s + xseg * 4;
    const uint32_t xso = (uint32_t)(xr0 * (PAD * 2) + xseg * 8);

    // W cp.async: 2 x 16B units per thread per chunk
    const int wu  = tid * 2;
    const int wn0 = wu >> 2,       wk0 = (wu & 3) * 8;
    const int wn1 = (wu + 1) >> 2, wk1 = ((wu + 1) & 3) * 8;

    // ---- prologue ----
    float4 xr[4];
    #pragma unroll
    for (int j = 0; j < 4; j++)
        xr[j] = *(const float4*)(xbase + (size_t)j * 32 * IN_F);

    cp16(&sm->ws[0][wn0][wk0], &g_w[t][wn0][wk0]);
    cp16(&sm->ws[0][wn1][wk1], &g_w[t][wn1][wk1]);
    asm volatile("cp.async.commit_group;" ::: "memory");
    cp16(&sm->ws[1][wn0][wk0], &g_w[t][wn0][KC + wk0]);
    cp16(&sm->ws[1][wn1][wk1], &g_w[t][wn1][KC + wk1]);
    asm volatile("cp.async.commit_group;" ::: "memory");

    #pragma unroll
    for (int ci = 0; ci < NCH; ci++) {
        const int st = ci % NSTG;

        // convert prefetched X regs -> fp16, STS.64 into stage st
        // (stage st last read by compute(ci-4): ordered by barrier(ci-3))
        {
            const uint32_t dst0 = XS + (uint32_t)st * 10240u + xso;
            #pragma unroll
            for (int j = 0; j < 4; j++) {
                float4 v = xr[j];
                __half2 h01 = __floats2half2_rn(v.x, v.y);
                __half2 h23 = __floats2half2_rn(v.z, v.w);
                asm volatile("st.shared.v2.b32 [%0], {%1,%2};"
                    :: "r"(dst0 + (uint32_t)j * 32u * (PAD * 2)),
                       "r"(*(uint32_t*)&h01), "r"(*(uint32_t*)&h23));
            }
        }

        // prefetch next X chunk (long-latency, issue early)
        if (ci + 1 < NCH) {
            const int kn = (ci + 1) * KC;
            #pragma unroll
            for (int j = 0; j < 4; j++)
                xr[j] = *(const float4*)(xbase + kn + (size_t)j * 32 * IN_F);
        }
        // prefetch W chunk ci+2 into stage (ci+2)%NSTG
        // (that stage last read by compute(ci-2): ordered by barrier(ci-1))
        if (ci + 2 < NCH) {
            const int kn = (ci + 2) * KC;
            const int ns = (ci + 2) % NSTG;
            cp16(&sm->ws[ns][wn0][wk0], &g_w[t][wn0][kn + wk0]);
            cp16(&sm->ws[ns][wn1][wk1], &g_w[t][wn1][kn + wk1]);
            asm volatile("cp.async.commit_group;" ::: "memory");
        }

        // wait for W chunk ci (leave later groups in flight)
        if (ci < NCH - 2)
            asm volatile("cp.async.wait_group 2;" ::: "memory");
        else if (ci == NCH - 2)
            asm volatile("cp.async.wait_group 1;" ::: "memory");
        else
            asm volatile("cp.async.wait_group 0;" ::: "memory");

        // single barrier per chunk: orders this chunk's STS/cp.async before
        // its compute, and (collectively) retires older-stage readers
        __syncthreads();

        // ---- compute chunk ci on stage st ----
        const uint32_t so = (uint32_t)st * 10240u;
        uint32_t bh[2][8];
        #pragma unroll
        for (int ks = 0; ks < 2; ks++) {
            #pragma unroll
            for (int np = 0; np < 2; np++)
                ldmx4(&bh[ks][np * 4], WS + so + boff + np * 1280 + ks * 32);
        }
        #pragma unroll
        for (int mf = 0; mf < 4; mf++) {
            uint32_t a0[4], a1[4];
            ldmx4(a0, XS + so + aoff + mf * 1280);
            ldmx4(a1, XS + so + aoff + mf * 1280 + 32);
            #pragma unroll
            for (int nf = 0; nf < 4; nf++) {
                MMA_F16(acc[mf][nf], a0, &bh[0][nf * 2]);
                MMA_F16(acc[mf][nf], a1, &bh[1][nf * 2]);
            }
        }
    }

    // ---- epilogue: add bias, store fp32 ----
    #pragma unroll
    for (int mf = 0; mf < 4; mf++) {
        int r = rt * TM + wm * 64 + mf * 16 + g;
        #pragma unroll
        for (int nf = 0; nf < 4; nf++) {
            int c = t * TN + wn * 32 + nf * 8 + 2 * t4;
            float2 bb = *(const float2*)&bias[c];
            float2 v0, v1;
            v0.x = acc[mf][nf][0] + bb.x;
            v0.y = acc[mf][nf][1] + bb.y;
            v1.x = acc[mf][nf][2] + bb.x;
            v1.y = acc[mf][nf][3] + bb.y;
            *(float2*)&out[(size_t)r * OUT_F + c]       = v0;
            *(float2*)&out[(size_t)(r + 8) * OUT_F + c] = v1;
        }
    }
}

extern "C" void kernel_launch(void* const* d_in, const int* in_sizes, int n_in,
                              void* d_out, int out_size) {
    const float* x    = (const float*)d_in[0];
    const float* w    = (const float*)d_in[1];
    const float* bias = (const float*)d_in[2];
    const float* mask = (const float*)d_in[3];
    float* out = (float*)d_out;

    cudaFuncSetAttribute(band_gemm_kernel,
                         cudaFuncAttributeMaxDynamicSharedMemorySize,
                         (int)SMEM_BYTES);

    prep_kernel<<<(NT * TN * KW + 255) / 256, 256>>>(w, mask);
    band_gemm_kernel<<<dim3(NT, BATCH / TM), 256, SMEM_BYTES>>>(x, bias, out);
}